// round 17
// baseline (speedup 1.0000x reference)
#include <cuda_runtime.h>
#include <cuda_bf16.h>
#include <cstdint>

#define XDIM 1024
#define KD 64            // output dim (N)
#define KC 64            // k-chunk
#define NCH (XDIM / KC)  // 16
#define ROWS 64
#define THREADS 128
#define NSTAGE 2

#define XS_STRIDE 68                        // floats per x row (pad 64->68)
#define XS_BYTES (ROWS * XS_STRIDE * 4)     // 17408
#define VS_PITCH 192                        // bytes per n-row (128B data, pad to 192)
#define VS_BYTES (KD * VS_PITCH)            // 12288 per (hi|lo) tile
#define STAGE_BYTES (XS_BYTES + 2 * VS_BYTES)  // 41984
#define OFF_W 0
#define OFF_S 4096
#define SMEM_BYTES (OFF_S + NSTAGE * STAGE_BYTES)   // 88064 -> 2 CTAs/SM

__device__ float g_w[XDIM];                               // w[i] = sum_k V[i][k]^2
// permuted-k layout: [n][chunk c][unit u (8 bf16)]
//   unit u = p2*4 + tt holds, for k16 pair (2p2, 2p2+1):
//   [v(32p2+2tt), +1, v(32p2+2tt+8), +1, v(32p2+16+2tt), +1, v(32p2+16+2tt+8), +1]
__device__ __align__(16) unsigned short g_vth[KD * XDIM];
__device__ __align__(16) unsigned short g_vtl[KD * XDIM];

__device__ __forceinline__ unsigned smaddr(const void* p) {
    return (unsigned)__cvta_generic_to_shared(p);
}
__device__ __forceinline__ void cp16(unsigned dst, const void* src) {
    asm volatile("cp.async.cg.shared.global [%0], [%1], 16;" :: "r"(dst), "l"(src));
}
__device__ __forceinline__ unsigned packbf(float a, float b) {
    unsigned short ha = __bfloat16_as_ushort(__float2bfloat16(a));
    unsigned short hb = __bfloat16_as_ushort(__float2bfloat16(b));
    return (unsigned)ha | ((unsigned)hb << 16);
}
__device__ __forceinline__ void split2(float2 f, unsigned& hi, unsigned& lo) {
    __nv_bfloat16 hx = __float2bfloat16(f.x);
    __nv_bfloat16 hy = __float2bfloat16(f.y);
    hi = (unsigned)__bfloat16_as_ushort(hx) | ((unsigned)__bfloat16_as_ushort(hy) << 16);
    lo = packbf(f.x - __bfloat162float(hx), f.y - __bfloat162float(hy));
}
__device__ __forceinline__ void mma16816(float* d, const unsigned* a,
                                         unsigned b0, unsigned b1) {
    asm volatile(
        "mma.sync.aligned.m16n8k16.row.col.f32.bf16.bf16.f32 "
        "{%0,%1,%2,%3}, {%4,%5,%6,%7}, {%8,%9}, {%0,%1,%2,%3};"
        : "+f"(d[0]), "+f"(d[1]), "+f"(d[2]), "+f"(d[3])
        : "r"(a[0]), "r"(a[1]), "r"(a[2]), "r"(a[3]), "r"(b0), "r"(b1));
}
__device__ __forceinline__ void split1(float f, unsigned short& hh, unsigned short& ll) {
    __nv_bfloat16 bh = __float2bfloat16(f);
    hh = __bfloat16_as_ushort(bh);
    ll = __bfloat16_as_ushort(__float2bfloat16(f - __bfloat162float(bh)));
}

// ---------------- prep: transpose + split V (permuted k-units), compute w ----------------
__global__ void prep_tc(const float* __restrict__ v) {
    __shared__ unsigned short th[KD][72];   // [n][i_local]
    __shared__ unsigned short tl[KD][72];
    const int b = blockIdx.x;               // 16 blocks, chunk c = b, i0 = b*64
    const int t = threadIdx.x;              // 256
    const int il = t >> 2, cq = t & 3;
    const int i = b * 64 + il;

    float wq = 0.f;
    #pragma unroll
    for (int j = 0; j < 4; j++) {
        float4 f = *(const float4*)(v + (size_t)i * KD + cq * 16 + j * 4);
        wq = fmaf(f.x, f.x, wq); wq = fmaf(f.y, f.y, wq);
        wq = fmaf(f.z, f.z, wq); wq = fmaf(f.w, f.w, wq);
        float vals[4] = {f.x, f.y, f.z, f.w};
        #pragma unroll
        for (int u = 0; u < 4; u++) {
            int n = cq * 16 + j * 4 + u;
            split1(vals[u], th[n][il], tl[n][il]);
        }
    }
    wq += __shfl_xor_sync(0xffffffffu, wq, 1);
    wq += __shfl_xor_sync(0xffffffffu, wq, 2);
    if (cq == 0) g_w[i] = wq;
    __syncthreads();

    // permuted writeout: thread -> row n = t>>2, units (t&3) and (t&3)+4
    const int n = t >> 2, un = t & 3;
    #pragma unroll
    for (int rr = 0; rr < 2; rr++) {
        int u = un + rr * 4;
        int p2 = u >> 2, tt = u & 3;
        int k0 = 32 * p2 + 2 * tt;
        int kidx[8] = { k0, k0 + 1, k0 + 8, k0 + 9,
                        k0 + 16, k0 + 17, k0 + 24, k0 + 25 };
        uint4 oh, ol;
        oh.x = (unsigned)th[n][kidx[0]] | ((unsigned)th[n][kidx[1]] << 16);
        oh.y = (unsigned)th[n][kidx[2]] | ((unsigned)th[n][kidx[3]] << 16);
        oh.z = (unsigned)th[n][kidx[4]] | ((unsigned)th[n][kidx[5]] << 16);
        oh.w = (unsigned)th[n][kidx[6]] | ((unsigned)th[n][kidx[7]] << 16);
        ol.x = (unsigned)tl[n][kidx[0]] | ((unsigned)tl[n][kidx[1]] << 16);
        ol.y = (unsigned)tl[n][kidx[2]] | ((unsigned)tl[n][kidx[3]] << 16);
        ol.z = (unsigned)tl[n][kidx[4]] | ((unsigned)tl[n][kidx[5]] << 16);
        ol.w = (unsigned)tl[n][kidx[6]] | ((unsigned)tl[n][kidx[7]] << 16);
        *(uint4*)(g_vth + (size_t)n * XDIM + b * 64 + u * 8) = oh;
        *(uint4*)(g_vtl + (size_t)n * XDIM + b * 64 + u * 8) = ol;
    }
}

// ---------------- main: split-bf16 mma.sync, LDS.128 B frags, race-free pipeline ----------------
__global__ __launch_bounds__(THREADS, 2)
void fm_mma(const float* __restrict__ x, float* __restrict__ out) {
    extern __shared__ __align__(128) char smem[];
    const unsigned sbase = smaddr(smem);
    const int tid = threadIdx.x;
    const int warp = tid >> 5;        // 0..3
    const int lane = tid & 31;
    const int g = lane >> 2;
    const int t = lane & 3;
    const size_t row0 = (size_t)blockIdx.x * ROWS;

    // stage w (1024 floats, 128 threads -> 2 float4 each)
    *(float4*)(smem + OFF_W + tid * 16) = *(const float4*)(g_w + tid * 4);
    *(float4*)(smem + OFF_W + (tid + THREADS) * 16) =
        *(const float4*)(g_w + (tid + THREADS) * 4);

    float acc[8][4];
    #pragma unroll
    for (int nf = 0; nf < 8; nf++)
        #pragma unroll
        for (int j = 0; j < 4; j++) acc[nf][j] = 0.f;
    float qg = 0.f, qg8 = 0.f;

    auto load_chunk = [&](int c, int s) {
        unsigned st = sbase + OFF_S + s * STAGE_BYTES;
        unsigned xsm = st;
        unsigned vh = st + XS_BYTES;
        unsigned vl = vh + VS_BYTES;
        // x tile: 64 rows x 64 floats = 1024 float4 -> 8 cp16 per thread
        #pragma unroll
        for (int nn = 0; nn < 8; nn++) {
            int u = tid + nn * THREADS;
            int r = u >> 4, cc = u & 15;
            cp16(xsm + r * (XS_STRIDE * 4) + cc * 16,
                 x + (row0 + r) * XDIM + c * KC + cc * 4);
        }
        // V hi/lo: 512 16B units each (permuted source), pitch 192B in smem
        #pragma unroll
        for (int nn = 0; nn < 4; nn++) {
            int u = tid + nn * THREADS;
            int row = u >> 3, o = u & 7;
            cp16(vh + row * VS_PITCH + o * 16,
                 g_vth + (size_t)row * XDIM + c * KC + o * 8);
        }
        #pragma unroll
        for (int nn = 0; nn < 4; nn++) {
            int u = tid + nn * THREADS;
            int row = u >> 3, o = u & 7;
            cp16(vl + row * VS_PITCH + o * 16,
                 g_vtl + (size_t)row * XDIM + c * KC + o * 8);
        }
        asm volatile("cp.async.commit_group;");
    };

    auto compute_chunk = [&](int c, int s) {
        const char* st = smem + OFF_S + s * STAGE_BYTES;
        const float* xsm = (const float*)st;
        const char* vsh = st + XS_BYTES;
        const char* vsl = vsh + VS_BYTES;
        const float* wsm = (const float*)(smem + OFF_W) + c * KC;

        // phase 1: x fragments + q-fold + all splits (A frags for 4 k16)
        unsigned ah[4][4], al[4][4];
        #pragma unroll
        for (int k16 = 0; k16 < 4; k16++) {
            const float* p = xsm + k16 * 16 + 2 * t;
            const float* r0 = p + (warp * 16 + g) * XS_STRIDE;
            const float* r8 = p + (warp * 16 + g + 8) * XS_STRIDE;
            float2 x0 = *(const float2*)(r0);
            float2 x1 = *(const float2*)(r8);
            float2 x2 = *(const float2*)(r0 + 8);
            float2 x3 = *(const float2*)(r8 + 8);
            float2 w0 = *(const float2*)(wsm + k16 * 16 + 2 * t);
            float2 w1 = *(const float2*)(wsm + k16 * 16 + 2 * t + 8);
            qg  = fmaf(x0.x * x0.x, w0.x, qg);
            qg  = fmaf(x0.y * x0.y, w0.y, qg);
            qg  = fmaf(x2.x * x2.x, w1.x, qg);
            qg  = fmaf(x2.y * x2.y, w1.y, qg);
            qg8 = fmaf(x1.x * x1.x, w0.x, qg8);
            qg8 = fmaf(x1.y * x1.y, w0.y, qg8);
            qg8 = fmaf(x3.x * x3.x, w1.x, qg8);
            qg8 = fmaf(x3.y * x3.y, w1.y, qg8);
            split2(x0, ah[k16][0], al[k16][0]);
            split2(x1, ah[k16][1], al[k16][1]);
            split2(x2, ah[k16][2], al[k16][2]);
            split2(x3, ah[k16][3], al[k16][3]);
        }

        // phase 2: B walk — one LDS.128 per (nf, k16-pair, hi/lo)
        #pragma unroll
        for (int p2 = 0; p2 < 2; p2++) {
            #pragma unroll
            for (int nf = 0; nf < 8; nf++) {
                const char* rb = vsh + (nf * 8 + g) * VS_PITCH + p2 * 64 + t * 16;
                const char* lb = vsl + (nf * 8 + g) * VS_PITCH + p2 * 64 + t * 16;
                uint4 H = *(const uint4*)rb;
                uint4 L = *(const uint4*)lb;
                // k16 = 2*p2
                mma16816(acc[nf], ah[2 * p2], H.x, H.y);
                mma16816(acc[nf], ah[2 * p2], L.x, L.y);
                mma16816(acc[nf], al[2 * p2], H.x, H.y);
                // k16 = 2*p2 + 1
                mma16816(acc[nf], ah[2 * p2 + 1], H.z, H.w);
                mma16816(acc[nf], ah[2 * p2 + 1], L.z, L.w);
                mma16816(acc[nf], al[2 * p2 + 1], H.z, H.w);
            }
        }
    };

    // prologue
    load_chunk(0, 0);

    // race-free skeleton (R6/R8-proven): wait own group, THEN barrier, then read
    #pragma unroll 1
    for (int c = 0; c < NCH; c++) {
        if (c + 1 < NCH) {
            load_chunk(c + 1, (c + 1) & 1);
            asm volatile("cp.async.wait_group 1;");
        } else {
            asm volatile("cp.async.wait_group 0;");
        }
        __syncthreads();                 // publish all threads' completed copies
        compute_chunk(c, c & 1);
        __syncthreads();                 // stage c&1 free before load(c+2) overwrites
    }

    // epilogue
    float sg = 0.f, sg8 = 0.f;
    #pragma unroll
    for (int nf = 0; nf < 8; nf++) {
        sg  = fmaf(acc[nf][0], acc[nf][0], sg);
        sg  = fmaf(acc[nf][1], acc[nf][1], sg);
        sg8 = fmaf(acc[nf][2], acc[nf][2], sg8);
        sg8 = fmaf(acc[nf][3], acc[nf][3], sg8);
    }
    sg  += __shfl_xor_sync(0xffffffffu, sg, 1);
    sg  += __shfl_xor_sync(0xffffffffu, sg, 2);
    sg8 += __shfl_xor_sync(0xffffffffu, sg8, 1);
    sg8 += __shfl_xor_sync(0xffffffffu, sg8, 2);
    qg  += __shfl_xor_sync(0xffffffffu, qg, 1);
    qg  += __shfl_xor_sync(0xffffffffu, qg, 2);
    qg8 += __shfl_xor_sync(0xffffffffu, qg8, 1);
    qg8 += __shfl_xor_sync(0xffffffffu, qg8, 2);
    if (t == 0) {
        out[row0 + warp * 16 + g]     = 0.5f * (sg - qg);
        out[row0 + warp * 16 + g + 8] = 0.5f * (sg8 - qg8);
    }
}

extern "C" void kernel_launch(void* const* d_in, const int* in_sizes, int n_in,
                              void* d_out, int out_size) {
    const float* x = (const float*)d_in[0];
    const float* v = (const float*)d_in[1];
    float* out = (float*)d_out;
    const int B = in_sizes[0] / XDIM;   // 16384

    prep_tc<<<XDIM / 64, 256>>>(v);

    cudaFuncSetAttribute(fm_mma, cudaFuncAttributeMaxDynamicSharedMemorySize, SMEM_BYTES);
    fm_mma<<<B / ROWS, THREADS, SMEM_BYTES>>>(x, out);
}